// round 15
// baseline (speedup 1.0000x reference)
#include <cuda_runtime.h>
#include <cuda_bf16.h>
#include <cstdint>

#define EDIM   128
#define NHEAD  4
#define HD     32
#define MAXN   65536
#define MAXB   512
#define MAXT   (MAXN + MAXB)
#define LCAP   256      // scalar-fallback smem staging cap
#define LP     176      // tensor attention max L (fallback beyond)

// ---------------- scratch (decomposed bf16 hi/lo everywhere) ----------------
__device__ __nv_bfloat16 g_valh[(size_t)MAXT * EDIM];
__device__ __nv_bfloat16 g_vall[(size_t)MAXT * EDIM];
__device__ __nv_bfloat16 g_qbh [(size_t)MAXT * EDIM];   // head-major [H][T][32], scaled
__device__ __nv_bfloat16 g_qbl [(size_t)MAXT * EDIM];
__device__ __nv_bfloat16 g_kbh [(size_t)MAXT * EDIM];
__device__ __nv_bfloat16 g_kbl [(size_t)MAXT * EDIM];
__device__ __nv_bfloat16 g_vbh [(size_t)MAXT * EDIM];
__device__ __nv_bfloat16 g_vbl [(size_t)MAXT * EDIM];
__device__ __nv_bfloat16 g_ctxh[(size_t)MAXT * EDIM];   // token-major [T][128]
__device__ __nv_bfloat16 g_ctxl[(size_t)MAXT * EDIM];
__device__ __nv_bfloat16 g_wbhi[6 * EDIM * EDIM];       // Wk,Wq,in_q,in_k,in_v,out
__device__ __nv_bfloat16 g_wblo[6 * EDIM * EDIM];
__device__ int   g_off  [MAXB + 1];
__device__ int   g_dest [MAXT];

// ---------------- helpers ----------------
__device__ __forceinline__ uint32_t smem_u32(const void* p) {
    uint32_t a;
    asm("{ .reg .u64 t; cvta.to.shared.u64 t, %1; cvt.u32.u64 %0, t; }" : "=r"(a) : "l"(p));
    return a;
}
__device__ __forceinline__ void ldsm4(uint32_t* r, uint32_t addr) {
    asm volatile("ldmatrix.sync.aligned.m8n8.x4.shared.b16 {%0,%1,%2,%3}, [%4];"
                 : "=r"(r[0]), "=r"(r[1]), "=r"(r[2]), "=r"(r[3]) : "r"(addr));
}
__device__ __forceinline__ void ldsm4t(uint32_t* r, uint32_t addr) {
    asm volatile("ldmatrix.sync.aligned.m8n8.x4.trans.shared.b16 {%0,%1,%2,%3}, [%4];"
                 : "=r"(r[0]), "=r"(r[1]), "=r"(r[2]), "=r"(r[3]) : "r"(addr));
}
__device__ __forceinline__ void mma_bf16(float* d, const uint32_t* a, const uint32_t* b) {
    asm volatile("mma.sync.aligned.m16n8k16.row.col.f32.bf16.bf16.f32 "
                 "{%0,%1,%2,%3}, {%4,%5,%6,%7}, {%8,%9}, {%0,%1,%2,%3};"
                 : "+f"(d[0]), "+f"(d[1]), "+f"(d[2]), "+f"(d[3])
                 : "r"(a[0]), "r"(a[1]), "r"(a[2]), "r"(a[3]), "r"(b[0]), "r"(b[1]));
}
__device__ __forceinline__ uint32_t pack_bf2(float a, float b) {
    __nv_bfloat162 t = __floats2bfloat162_rn(a, b);
    return *(uint32_t*)&t;
}
__device__ __forceinline__ float bf16_rt(float x) {
    return __bfloat162float(__float2bfloat16(x));
}
__device__ __forceinline__ void cp16(uint32_t dst, const void* src, bool valid) {
    int sz = valid ? 16 : 0;
    asm volatile("cp.async.cg.shared.global [%0], [%1], 16, %2;"
                 :: "r"(dst), "l"(src), "r"(sz) : "memory");
}
#define CP_COMMIT() asm volatile("cp.async.commit_group;" ::: "memory")
#define CP_WAIT0()  asm volatile("cp.async.wait_group 0;" ::: "memory")

// ---------------- small setup kernels ----------------
__global__ void offsets_kernel(const int* __restrict__ batch, int N, int nB, int* __restrict__ off)
{
    int g = blockIdx.x * blockDim.x + threadIdx.x;
    if (g > nB) return;
    if (g == nB) { off[nB] = N; return; }
    int lo = 0, hi = N;
    while (lo < hi) { int m = (lo + hi) >> 1; if (batch[m] < g) lo = m + 1; else hi = m; }
    off[g] = lo;
}

__global__ void gather_kernel(const float* __restrict__ x, const float* __restrict__ mx,
                              const int* __restrict__ batch, const int* __restrict__ off,
                              int N, int nB,
                              __nv_bfloat16* __restrict__ valh, __nv_bfloat16* __restrict__ vall,
                              int* __restrict__ dest)
{
    int row  = blockIdx.x * 8 + (threadIdx.x >> 5);
    int lane = threadIdx.x & 31;
    const float* src = nullptr;
    int tok = -1, drow = 0;
    if (row < N) {
        int g = batch[row]; tok = row + g + 1; drow = row;
        src = x + (size_t)row * EDIM;
    } else if (row < N + nB) {
        int g = row - N; tok = off[g] + g; drow = N + g;
        src = mx + (size_t)g * EDIM;
    } else return;
    float4 v4 = *(const float4*)(src + lane * 4);
    float h0 = bf16_rt(v4.x), h1 = bf16_rt(v4.y), h2 = bf16_rt(v4.z), h3 = bf16_rt(v4.w);
    size_t o = (size_t)tok * EDIM + lane * 4;
    *(uint2*)(valh + o) = make_uint2(pack_bf2(h0, h1), pack_bf2(h2, h3));
    *(uint2*)(vall + o) = make_uint2(pack_bf2(v4.x - h0, v4.y - h1), pack_bf2(v4.z - h2, v4.w - h3));
    if (lane == 0) dest[tok] = drow;
}

__global__ void wdecomp_kernel(const float* __restrict__ Wk, const float* __restrict__ Wq,
                               const float* __restrict__ in_w, const float* __restrict__ out_w,
                               __nv_bfloat16* __restrict__ bhi, __nv_bfloat16* __restrict__ blo)
{
    int idx = blockIdx.x * 256 + threadIdx.x;
    if (idx >= 6 * EDIM * EDIM) return;
    int slab = idx >> 14, r = idx & 16383;
    float v = (slab == 0) ? Wk[r] : (slab == 1) ? Wq[r]
            : (slab < 5)  ? in_w[(size_t)(slab - 2) * EDIM * EDIM + r] : out_w[r];
    __nv_bfloat16 h = __float2bfloat16(v);
    bhi[idx] = h;
    blo[idx] = __float2bfloat16(v - __bfloat162float(h));
}

// ================= pipelined 3xBF16 GEMM core =================
struct Frags {
    uint32_t ah[2][4], al[2][4];
    uint32_t bh[4][2], bl[4][2];
};

__device__ __forceinline__ void load_frags(uint32_t sb, uint32_t aHi, uint32_t aLo,
                                           uint32_t bHi, uint32_t bLo,
                                           int kb, int m0, int n0, int lr, Frags& f)
{
    #pragma unroll
    for (int im = 0; im < 2; im++) {
        int row = m0 + im * 16 + lr;
        uint32_t off = row * 256 + ((kb ^ (row & 7)) << 4);
        ldsm4(f.ah[im], sb + aHi + off);
        ldsm4(f.al[im], sb + aLo + off);
    }
    #pragma unroll
    for (int p = 0; p < 2; p++) {
        int row = n0 + p * 16 + lr;
        uint32_t off = row * 256 + ((kb ^ (row & 7)) << 4);
        uint32_t rh[4], rl[4];
        ldsm4(rh, sb + bHi + off);
        ldsm4(rl, sb + bLo + off);
        f.bh[2*p+0][0] = rh[0]; f.bh[2*p+0][1] = rh[2];
        f.bh[2*p+1][0] = rh[1]; f.bh[2*p+1][1] = rh[3];
        f.bl[2*p+0][0] = rl[0]; f.bl[2*p+0][1] = rl[2];
        f.bl[2*p+1][0] = rl[1]; f.bl[2*p+1][1] = rl[3];
    }
}

__device__ __forceinline__ void mma_frags(float acc[2][4][4], const Frags& f)
{
    #pragma unroll
    for (int im = 0; im < 2; im++)
        #pragma unroll
        for (int in = 0; in < 4; in++) {
            mma_bf16(acc[im][in], f.ah[im], f.bh[in]);
            mma_bf16(acc[im][in], f.ah[im], f.bl[in]);
            mma_bf16(acc[im][in], f.al[im], f.bh[in]);
        }
}

// software-pipelined full-K GEMM: ping-pong frag buffers hide ldsm latency
__device__ __forceinline__ void compute_full(uint32_t sb, float acc[2][4][4],
                                             uint32_t aHi, uint32_t aLo,
                                             uint32_t bHi, uint32_t bLo,
                                             int wid, int lane)
{
    const int wm = wid & 1, wn = wid >> 1;
    const int m0 = wm * 32, n0 = wn * 32;
    const int lr = lane & 15, lc = lane >> 4;

    #pragma unroll
    for (int im = 0; im < 2; im++)
        #pragma unroll
        for (int in = 0; in < 4; in++)
            #pragma unroll
            for (int c = 0; c < 4; c++) acc[im][in][c] = 0.f;

    Frags f0, f1;
    load_frags(sb, aHi, aLo, bHi, bLo, lc, m0, n0, lr, f0);          // k16=0
    #pragma unroll 1
    for (int k2 = 0; k2 < 4; k2++) {
        load_frags(sb, aHi, aLo, bHi, bLo, (2*k2+1)*2 + lc, m0, n0, lr, f1);
        mma_frags(acc, f0);
        if (k2 < 3)
            load_frags(sb, aHi, aLo, bHi, bLo, (2*k2+2)*2 + lc, m0, n0, lr, f0);
        mma_frags(acc, f1);
    }
}

// ================= fused5: cp.async double-buffered weights, A resident =================
// 192KB smem, 1 CTA/SM. A: hi@0 lo@16K. X: hi@32K lo@48K. B0: hi@64K lo@96K. B1: hi@128K lo@160K.
#define FA_HI  0
#define FA_LO  16384
#define FX_HI  32768
#define FX_LO  49152
#define B0_HI  65536
#define B0_LO  98304
#define B1_HI  131072
#define B1_LO  163840
#define FUSED_SMEM 196608

__device__ __forceinline__ void ca_stage_A(const __nv_bfloat16* __restrict__ Ah,
                                           const __nv_bfloat16* __restrict__ Al,
                                           int tile0, int T, uint32_t sb, int tid)
{
    #pragma unroll
    for (int i = 0; i < 4; i++) {
        int f   = tid + i * 256;
        int row = f >> 4;
        int grp = f & 15;
        bool v  = (tile0 + row) < T;
        int srow = v ? (tile0 + row) : 0;
        uint32_t off = row * 256 + ((grp ^ (row & 7)) << 4);
        cp16(sb + FA_HI + off, Ah + (size_t)srow * EDIM + grp * 8, v);
        cp16(sb + FA_LO + off, Al + (size_t)srow * EDIM + grp * 8, v);
    }
}

__device__ __forceinline__ void ca_stage_B(const __nv_bfloat16* __restrict__ Bhi,
                                           const __nv_bfloat16* __restrict__ Blo,
                                           uint32_t sb, int tid, uint32_t rbHi, uint32_t rbLo)
{
    #pragma unroll
    for (int i = 0; i < 8; i++) {
        int f   = tid + i * 256;
        int row = f >> 4;
        int grp = f & 15;
        uint32_t off = row * 256 + ((grp ^ (row & 7)) << 4);
        cp16(sb + rbHi + off, Bhi + (size_t)row * EDIM + grp * 8, true);
        cp16(sb + rbLo + off, Blo + (size_t)row * EDIM + grp * 8, true);
    }
}

// epilogue: bias+relu, decompose, write to smem X region in A-stage format
__device__ __forceinline__ void epi_to_X(const float acc[2][4][4], const float* __restrict__ bias,
                                         char* smem, int wid, int lane)
{
    const int wm = wid & 1, wn = wid >> 1;
    const int m0 = wm * 32, n0 = wn * 32;
    const int gid = lane >> 2, tig = lane & 3;
    #pragma unroll
    for (int in = 0; in < 4; in++) {
        int col = n0 + in * 8 + tig * 2;
        float2 b2 = *(const float2*)(bias + col);
        int grp = col >> 3, within = (col & 7) * 2;
        #pragma unroll
        for (int im = 0; im < 2; im++)
            #pragma unroll
            for (int rh = 0; rh < 2; rh++) {
                int row = m0 + im * 16 + gid + rh * 8;
                float v0 = fmaxf(acc[im][in][rh*2+0] + b2.x, 0.f);
                float v1 = fmaxf(acc[im][in][rh*2+1] + b2.y, 0.f);
                float h0 = bf16_rt(v0), h1 = bf16_rt(v1);
                uint32_t off = row * 256 + ((grp ^ (row & 7)) << 4) + within;
                *(uint32_t*)(smem + FX_HI + off) = pack_bf2(h0, h1);
                *(uint32_t*)(smem + FX_LO + off) = pack_bf2(v0 - h0, v1 - h1);
            }
    }
}

// epilogue: decomposed head-major [H][T][32] with scale
__device__ __forceinline__ void epi_head_decomp(const float acc[2][4][4], const float* __restrict__ bias,
                                                __nv_bfloat16* __restrict__ Ch, __nv_bfloat16* __restrict__ Cl,
                                                int tile0, int T, float scale, int wid, int lane)
{
    const int wm = wid & 1, wn = wid >> 1;
    const int m0 = wm * 32, n0 = wn * 32;
    const int gid = lane >> 2, tig = lane & 3;
    #pragma unroll
    for (int in = 0; in < 4; in++) {
        int col = n0 + in * 8 + tig * 2;
        float2 b2 = *(const float2*)(bias + col);
        int hh = col >> 5, ci = col & 31;
        #pragma unroll
        for (int im = 0; im < 2; im++)
            #pragma unroll
            for (int rh = 0; rh < 2; rh++) {
                int row = m0 + im * 16 + gid + rh * 8;
                if (tile0 + row >= T) continue;
                float v0 = (acc[im][in][rh*2+0] + b2.x) * scale;
                float v1 = (acc[im][in][rh*2+1] + b2.y) * scale;
                float h0 = bf16_rt(v0), h1 = bf16_rt(v1);
                size_t o = ((size_t)hh * T + tile0 + row) * HD + ci;
                *(uint32_t*)(Ch + o) = pack_bf2(h0, h1);
                *(uint32_t*)(Cl + o) = pack_bf2(v0 - h0, v1 - h1);
            }
    }
}

__global__ __launch_bounds__(256, 1)
void gemm_fused5(const __nv_bfloat16* __restrict__ Avh, const __nv_bfloat16* __restrict__ Avl,
                 const __nv_bfloat16* __restrict__ wbhi, const __nv_bfloat16* __restrict__ wblo,
                 const float* __restrict__ bk, const float* __restrict__ bq,
                 const float* __restrict__ in_b,
                 __nv_bfloat16* __restrict__ qbh, __nv_bfloat16* __restrict__ qbl,
                 __nv_bfloat16* __restrict__ kbh, __nv_bfloat16* __restrict__ kbl,
                 __nv_bfloat16* __restrict__ vbh, __nv_bfloat16* __restrict__ vbl,
                 int T, float scaleQ)
{
    extern __shared__ char smem[];
    const uint32_t sb = smem_u32(smem);
    const int tid = threadIdx.x, wid = tid >> 5, lane = tid & 31;
    const int tile0 = blockIdx.x * 64;
    const int W = EDIM * EDIM;
    float acc[2][4][4];

    // initial: A(value) + Wk
    ca_stage_A(Avh, Avl, tile0, T, sb, tid);
    ca_stage_B(wbhi + 0*W, wblo + 0*W, sb, tid, B0_HI, B0_LO);
    CP_COMMIT(); CP_WAIT0();
    __syncthreads();

    // G1: kin = relu(value@Wk^T)   [A,B0]; prefetch in_k -> B1
    ca_stage_B(wbhi + 3*W, wblo + 3*W, sb, tid, B1_HI, B1_LO); CP_COMMIT();
    compute_full(sb, acc, FA_HI, FA_LO, B0_HI, B0_LO, wid, lane);
    epi_to_X(acc, bk, smem, wid, lane);
    CP_WAIT0(); __syncthreads();

    // G2: k = kin@in_k^T           [X,B1]; prefetch Wq -> B0
    ca_stage_B(wbhi + 1*W, wblo + 1*W, sb, tid, B0_HI, B0_LO); CP_COMMIT();
    compute_full(sb, acc, FX_HI, FX_LO, B1_HI, B1_LO, wid, lane);
    epi_head_decomp(acc, in_b + 128, kbh, kbl, tile0, T, 1.0f, wid, lane);
    CP_WAIT0(); __syncthreads();

    // G3: qin = relu(value@Wq^T)   [A,B0]; prefetch in_q -> B1
    ca_stage_B(wbhi + 2*W, wblo + 2*W, sb, tid, B1_HI, B1_LO); CP_COMMIT();
    compute_full(sb, acc, FA_HI, FA_LO, B0_HI, B0_LO, wid, lane);
    epi_to_X(acc, bq, smem, wid, lane);
    CP_WAIT0(); __syncthreads();

    // G4: q = (qin@in_q^T)*scale   [X,B1]; prefetch in_v -> B0
    ca_stage_B(wbhi + 4*W, wblo + 4*W, sb, tid, B0_HI, B0_LO); CP_COMMIT();
    compute_full(sb, acc, FX_HI, FX_LO, B1_HI, B1_LO, wid, lane);
    epi_head_decomp(acc, in_b, qbh, qbl, tile0, T, scaleQ, wid, lane);
    CP_WAIT0(); __syncthreads();

    // G5: v = value@in_v^T         [A,B0]
    compute_full(sb, acc, FA_HI, FA_LO, B0_HI, B0_LO, wid, lane);
    epi_head_decomp(acc, in_b + 256, vbh, vbl, tile0, T, 1.0f, wid, lane);
}

// ================= out projection: ctx(decomposed) -> fp32 out with dest scatter =================
#define GA_HI 0
#define GA_LO 16384
#define GB_HI 32768
#define GB_LO 65536
#define GEMM_SMEM 98304

__global__ __launch_bounds__(256, 2)
void gemm_singleOut(const __nv_bfloat16* __restrict__ Ah, const __nv_bfloat16* __restrict__ Al,
                    const __nv_bfloat16* __restrict__ Bhi, const __nv_bfloat16* __restrict__ Blo,
                    const float* __restrict__ bias, float* __restrict__ C,
                    const int* __restrict__ dest, int T)
{
    extern __shared__ char smem[];
    const uint32_t sb = smem_u32(smem);
    const int tid = threadIdx.x, wid = tid >> 5, lane = tid & 31;
    const int tile0 = blockIdx.x * 64;

    #pragma unroll
    for (int i = 0; i < 4; i++) {
        int f   = tid + i * 256;
        int row = f >> 4;
        int grp = f & 15;
        bool v  = (tile0 + row) < T;
        int srow = v ? (tile0 + row) : 0;
        uint32_t off = row * 256 + ((grp ^ (row & 7)) << 4);
        cp16(sb + GA_HI + off, Ah + (size_t)srow * EDIM + grp * 8, v);
        cp16(sb + GA_LO + off, Al + (size_t)srow * EDIM + grp * 8, v);
    }
    #pragma unroll
    for (int i = 0; i < 8; i++) {
        int f   = tid + i * 256;
        int row = f >> 4;
        int grp = f & 15;
        uint32_t off = row * 256 + ((grp ^ (row & 7)) << 4);
        cp16(sb + GB_HI + off, Bhi + (size_t)row * EDIM + grp * 8, true);
        cp16(sb + GB_LO + off, Blo + (size_t)row * EDIM + grp * 8, true);
    }
    CP_COMMIT(); CP_WAIT0();
    __syncthreads();

    float acc[2][4][4];
    compute_full(sb, acc, GA_HI, GA_LO, GB_HI, GB_LO, wid, lane);

    const int wm = wid & 1, wn = wid >> 1;
    const int m0 = wm * 32, n0 = wn * 32;
    const int gid = lane >> 2, tig = lane & 3;
    #pragma unroll
    for (int in = 0; in < 4; in++) {
        int col = n0 + in * 8 + tig * 2;
        float2 b2 = *(const float2*)(bias + col);
        #pragma unroll
        for (int im = 0; im < 2; im++)
            #pragma unroll
            for (int rh = 0; rh < 2; rh++) {
                int row = m0 + im * 16 + gid + rh * 8;
                if (tile0 + row >= T) continue;
                int orow = dest[tile0 + row];
                *(float2*)(C + (size_t)orow * EDIM + col) =
                    make_float2(acc[im][in][rh*2+0] + b2.x, acc[im][in][rh*2+1] + b2.y);
            }
    }
}

// ================= flash-style tensor-core attention (320 threads, unchanged) =================
#define SQ_HI 0
#define SQ_LO 14080
#define SK_HI 28160
#define SK_LO 42240
#define SV_HI 56320
#define SV_LO 70400
#define ATTN_TC_SMEM 84480

__global__ __launch_bounds__(320, 2)
void attn_tc_kernel(const __nv_bfloat16* __restrict__ qbh, const __nv_bfloat16* __restrict__ qbl,
                    const __nv_bfloat16* __restrict__ kbh, const __nv_bfloat16* __restrict__ kbl,
                    const __nv_bfloat16* __restrict__ vbh, const __nv_bfloat16* __restrict__ vbl,
                    __nv_bfloat16* __restrict__ ctxh, __nv_bfloat16* __restrict__ ctxl,
                    const int* __restrict__ off, int T)
{
    extern __shared__ char smem[];
    const uint32_t sb = smem_u32(smem);
    int g = blockIdx.x, h = blockIdx.y;
    int t0 = off[g] + g;
    int L  = off[g + 1] - off[g] + 1;
    if (L > LP) return;                      // scalar fallback handles
    int Lpad = (L + 15) & ~15;

    const int tid = threadIdx.x;
    const char* qh_b = (const char*)(qbh + (size_t)h * T * HD);
    const char* ql_b = (const char*)(qbl + (size_t)h * T * HD);
    const char* kh_b = (const char*)(kbh + (size_t)h * T * HD);
    const char* kl_b = (const char*)(kbl + (size_t)h * T * HD);
    const char* vh_b = (const char*)(vbh + (size_t)h * T * HD);
    const char* vl_b = (const char*)(vbl + (size_t)h * T * HD);

    for (int m = tid; m < Lpad; m += 320) {
        if (m < L) {
            size_t go = (size_t)(t0 + m) * 64;
            #pragma unroll
            for (int g4 = 0; g4 < 4; g4++) {
                uint32_t so = (uint32_t)m * 80 + g4 * 16;
                *(uint4*)(smem + SQ_HI + so) = *(const uint4*)(qh_b + go + g4 * 16);
                *(uint4*)(smem + SQ_LO + so) = *(const uint4*)(ql_b + go + g4 * 16);
                *(uint4*)(smem + SK_HI + so) = *(const uint4*)(kh_b + go + g4 * 16);
                *(uint4*)(smem + SK_LO + so) = *(const uint4*)(kl_b + go + g4 * 16);
                *(uint4*)(smem + SV_HI + so) = *(const uint4*)(vh_b + go + g4 * 16);
                *(uint4*)(smem + SV_LO + so) = *(const uint4*)(vl_b + go + g4 * 16);
            }
        } else {
            uint4 z = make_uint4(0,0,0,0);
            #pragma unroll
            for (int g4 = 0; g4 < 4; g4++) {
                uint32_t so = (uint32_t)m * 80 + g4 * 16;
                *(uint4*)(smem + SQ_HI + so) = z; *(uint4*)(smem + SQ_LO + so) = z;
                *(uint4*)(smem + SK_HI + so) = z; *(uint4*)(smem + SK_LO + so) = z;
                *(uint4*)(smem + SV_HI + so) = z; *(uint4*)(smem + SV_LO + so) = z;
            }
        }
    }
    __syncthreads();

    const int w = tid >> 5, lane = tid & 31;
    const int lr = lane & 15, lc = lane >> 4;
    const int kAct = (L + 15) >> 4;
    const uint32_t vrow = ((lane >> 3) & 1) * 8 + (lane & 7);
    const uint32_t vcol = (lane >> 4) * 8;
    const int tig2 = (lane & 3) << 1;

    for (int m0 = w * 16; m0 < L; m0 += 160) {
        uint32_t qfh[2][4], qfl[2][4];
        #pragma unroll
        for (int s = 0; s < 2; s++) {
            uint32_t a = sb + SQ_HI + (uint32_t)(m0 + lr) * 80 + s * 32 + lc * 16;
            ldsm4(qfh[s], a);
            ldsm4(qfl[s], a + (SQ_LO - SQ_HI));
        }
        float mr0 = -1e30f, mr1 = -1e30f, l0 = 0.f, l1 = 0.f;
        float cacc[4][4];
        #pragma unroll
        for (int n = 0; n < 4; n++) { cacc[n][0]=0.f; cacc[n][1]=0.f; cacc[n][2]=0.f; cacc[n][3]=0.f; }

        #pragma unroll 1
        for (int kt = 0; kt < kAct; kt++) {
            float s[2][4];
            s[0][0]=0.f; s[0][1]=0.f; s[0][2]=0.f; s[0][3]=0.f;
            s[1][0]=0.f; s[1][1]=0.f; s[1][2]=0.f; s[1][3]=0.f;
            #pragma unroll
            for (int st = 0; st < 2; st++) {
                uint32_t a = sb + SK_HI + (uint32_t)(kt * 16 + lr) * 80 + st * 32 + lc * 16;
                uint32_t kh[4], kl[4];
                ldsm4(kh, a);
                ldsm4(kl, a + (SK_LO - SK_HI));
                uint32_t bh0[2] = {kh[0], kh[2]}, bh1[2] = {kh[1], kh[3]};
                uint32_t bl0[2] = {kl[0], kl[2]}, bl1[2] = {kl[1], kl[3]};
                mma_bf16(s[0], qfh[st], bh0); mma_bf16(s[0], qfh[st], bl0); mma_bf16(s[0], qfl[st], bh0);
                mma_bf16(s[1], qfh[st], bh1); mma_bf16(s[1], qfh[st], bl1); mma_bf16(s[1], qfl[st], bh1);
            }
            if (kt == kAct - 1) {
                #pragma unroll
                for (int half = 0; half < 2; half++) {
                    int ck = kt * 16 + half * 8 + tig2;
                    if (ck >= L)     { s[half][0] = -1e30f; s[half][2] = -1e30f; }
                    if (ck + 1 >= L) { s[half][1] = -1e30f; s[half][3] = -1e30f; }
                }
            }
            float tm0 = fmaxf(fmaxf(s[0][0], s[0][1]), fmaxf(s[1][0], s[1][1]));
            float tm1 = fmaxf(fmaxf(s[0][2], s[0][3]), fmaxf(s[1][2], s[1][3]));
            tm0 = fmaxf(tm0, __shfl_xor_sync(0xffffffffu, tm0, 1));
            tm0 = fmaxf(tm0, __shfl_xor_sync(0xffffffffu, tm0, 2));
            tm1 = fmaxf(tm1, __shfl_xor_sync(0xffffffffu, tm1, 1));
            tm1 = fmaxf(tm1, __shfl_xor_sync(0xffffffffu, tm1, 2));
            float nm0 = fmaxf(mr0, tm0), nm1 = fmaxf(mr1, tm1);
            float c0 = __expf(mr0 - nm0), c1 = __expf(mr1 - nm1);
            mr0 = nm0; mr1 = nm1;
            float p[2][4];
            #pragma unroll
            for (int half = 0; half < 2; half++) {
                p[half][0] = __expf(s[half][0] - nm0);
                p[half][1] = __expf(s[half][1] - nm0);
                p[half][2] = __expf(s[half][2] - nm1);
                p[half][3] = __expf(s[half][3] - nm1);
            }
            float rs0 = p[0][0] + p[0][1] + p[1][0] + p[1][1];
            float rs1 = p[0][2] + p[0][3] + p[1][2] + p[1][3];
            rs0 += __shfl_xor_sync(0xffffffffu, rs0, 1);
            rs0 += __shfl_xor_sync(0xffffffffu, rs0, 2);
            rs1 += __shfl_xor_sync(0xffffffffu, rs1, 1);
            rs1 += __shfl_xor_sync(0xffffffffu, rs1, 2);
            l0 = l0 * c0 + rs0;
            l1 = l1 * c1 + rs1;
            #pragma unroll
            for (int n = 0; n < 4; n++) {
                cacc[n][0] *= c0; cacc[n][1] *= c0;
                cacc[n][2] *= c1; cacc[n][3] *= c1;
            }
            uint32_t pfh[4], pfl[4];
            #pragma unroll
            for (int half = 0; half < 2; half++) {
                float h0 = bf16_rt(p[half][0]), h1 = bf16_rt(p[half][1]);
                float h2 = bf16_rt(p[half][2]), h3 = bf16_rt(p[half][3]);
                pfh[2*half + 0] = pack_bf2(h0, h1);
                pfh[2*half + 1] = pack_bf2(h2, h3);
                pfl[2*half + 0] = pack_bf2(p[half][0] - h0, p[half][1] - h1);
                pfl[2*half + 1] = pack_bf2(p[half][2] - h2, p[half][3] - h3);
            }
            #pragma unroll
            for (int ng = 0; ng < 2; ng++) {
                uint32_t a = sb + SV_HI + (uint32_t)(kt * 16 + vrow) * 80 + (ng * 16 + vcol) * 2;
                uint32_t vh[4], vl[4];
                ldsm4t(vh, a);
                ldsm4t(vl, a + (SV_LO - SV_HI));
                uint32_t bh0[2] = {vh[0], vh[1]}, bh1[2] = {vh[2], vh[3]};
                uint32_t bl0[2] = {vl[0], vl[1]}, bl1[2] = {vl[2], vl[3]};
                mma_bf16(cacc[2*ng],   pfh, bh0);
                mma_bf16(cacc[2*ng],   pfh, bl0);
                mma_bf16(cacc[2*ng],   pfl, bh0);
                mma_bf16(cacc[2*ng+1], pfh, bh1);
                mma_bf16(cacc[2*ng+1], pfh, bl1);
                mma_bf16(cacc[2*ng+1], pfl, bh1);
            }
        }
        float i0 = 1.f / l0, i1 = 1.f / l1;
        int r0 = m0 + (lane >> 2), r1 = r0 + 8;
        #pragma unroll
        for (int nt = 0; nt < 4; nt++) {
            int col = nt * 8 + tig2;
            if (r0 < L) {
                float c0v = cacc[nt][0] * i0, c1v = cacc[nt][1] * i0;
                float h0 = bf16_rt(c0v), h1 = bf16_rt(c1v);
                size_t o = (size_t)(t0 + r0) * EDIM + h * HD + col;
                *(uint32_t*)(ctxh + o) = pack_bf2(h0, h1);
                *(uint32_t*)(ctxl + o) = pack_bf2(c0v - h0, c1v - h1);
            }
            if (r1 < L) {
                float c0v = cacc[nt][2] * i1, c1v = cacc[nt][3] * i1;
                float h0 = bf16_rt(c0v), h1 = bf16_rt(c1v);
                size_t o = (size_t)(t0 + r1) * EDIM + h * HD + col;
                *(uint32_t*)(ctxh + o) = pack_bf2(h0, h1);
                *(uint32_t*)(ctxl + o) = pack_bf2(c0v - h0, c1v - h1);
            }
        }
    }
}

// ---------------- scalar fallback attention (only L > LP) ----------------
#define ATTN_SMEM (2 * LCAP * HD * 4)

__global__ __launch_bounds__(192)
void attn_kernel(const __nv_bfloat16* __restrict__ qbh, const __nv_bfloat16* __restrict__ qbl,
                 const __nv_bfloat16* __restrict__ kbh, const __nv_bfloat16* __restrict__ kbl,
                 const __nv_bfloat16* __restrict__ vbh, const __nv_bfloat16* __restrict__ vbl,
                 __nv_bfloat16* __restrict__ ctxh, __nv_bfloat16* __restrict__ ctxl,
                 const int* __restrict__ off, int T)
{
    extern __shared__ float sm[];
    float* Ks = sm;
    float* Vs = sm + LCAP * HD;

    int g = blockIdx.x, h = blockIdx.y;
    int t0 = off[g] + g;
    int L  = off[g + 1] - off[g] + 1;
    if (L <= LP) return;
    int Ls = L < LCAP ? L : LCAP;
    int tid = threadIdx.x;

    const __nv_bfloat16* kh = kbh + (size_t)h * T * HD;
    const __nv_bfloat16* kl = kbl + (size_t)h * T * HD;
    const __nv_bfloat16* vh = vbh + (size_t)h * T * HD;
    const __nv_bfloat16* vl = vbl + (size_t)h * T * HD;
    const __nv_bfloat16* qh = qbh + (size_t)h * T * HD;
    const __nv_bfloat16* ql = qbl + (size_t)h * T * HD;

    for (int idx = tid; idx < Ls * HD; idx += blockDim.x) {
        size_t o = (size_t)t0 * HD + idx;
        Ks[idx] = __bfloat162float(kh[o]) + __bfloat162float(kl[o]);
        Vs[idx] = __bfloat162float(vh[o]) + __bfloat162float(vl[o]);
    }
    __syncthreads();

    for (int qi = tid; qi < L; qi += blockDim.x) {
        float qr[32];
        size_t qo = (size_t)(t0 + qi) * HD;
        #pragma unroll
        for (int j = 0; j < 32; j++)
            qr[j] = __bfloat162float(qh[qo + j]) + __bfloat162float(ql[qo + j]);
        float mx = -1e30f, s = 0.f;
        float acc[32];
        #pragma unroll
        for (int j = 0; j < 32; j++) acc[j] = 0.f;
        for (int mk = 0; mk < L; mk++) {
            float kr[32];
            if (mk < Ls) {
                #pragma unroll
                for (int j = 0; j < 32; j++) kr[j] = Ks[mk * HD + j];
            } else {
                size_t o = (size_t)(t0 + mk) * HD;
                #pragma unroll
                for (int j = 0; j < 32; j++)
                    kr[j] = __bfloat162float(kh[o + j]) + __bfloat162float(kl[o + j]);
            }
            float d0 = 0.f, d1 = 0.f, d2 = 0.f, d3 = 0.f;
            #pragma unroll
            for (int j4 = 0; j4 < 8; j4++) {
                d0 += qr[j4*4+0] * kr[j4*4+0]; d1 += qr[j4*4+1] * kr[j4*4+1];
                d2 += qr[j4*4+2] * kr[j4*4+2]; d3 += qr[j4*4+3] * kr[j4*4+3];
            }
            float xv = (d0 + d1) + (d2 + d3);
            float p;
            if (xv > mx) {
                float c = __expf(mx - xv);
                s *= c;
                #pragma unroll
                for (int j = 0; j < 32; j++) acc[j] *= c;
                mx = xv; p = 1.f;
            } else p = __expf(xv - mx);
            s += p;
            if (mk < Ls) {
                #pragma unroll
                for (int j = 0; j < 32; j++) acc[j] += p * Vs[mk * HD + j];
            } else {
                size_t o = (size_t)(t0 + mk) * HD;
                #pragma unroll
                for (int j = 0; j < 32; j++)
                    acc[j] += p * (__bfloat162float(vh[o + j]) + __bfloat162float(vl[o + j]));
            }
        }
        float inv = 1.f / s;
        size_t co = (size_t)(t0 + qi) * EDIM + h * HD;
        #pragma unroll
        for (int j2 = 0; j2 < 16; j2++) {
            float c0 = acc[j2*2+0] * inv, c1 = acc[j2*2+1] * inv;
            float h0 = bf16_rt(c0), h1 = bf16_rt(c1);
            *(uint32_t*)(ctxh + co + j2*2) = pack_bf2(h0, h1);
            *(uint32_t*)(ctxl + co + j2*2) = pack_bf2(c0 - h0, c1 - h1);
        }
    }
}

// ---------------- launch ----------------
extern "C" void kernel_launch(void* const* d_in, const int* in_sizes, int n_in,
                              void* d_out, int out_size)
{
    const float* x       = (const float*)d_in[0];
    const float* metal_x = (const float*)d_in[1];
    const int*   batch   = (const int*)  d_in[2];
    const float* Wk      = (const float*)d_in[3];
    const float* bk      = (const float*)d_in[4];
    const float* Wq      = (const float*)d_in[5];
    const float* bq      = (const float*)d_in[6];
    const float* in_w    = (const float*)d_in[7];
    const float* in_b    = (const float*)d_in[8];
    const float* out_w   = (const float*)d_in[9];
    const float* out_b   = (const float*)d_in[10];
    float* out = (float*)d_out;

    int N  = in_sizes[0] / EDIM;
    int nB = in_sizes[1] / EDIM;
    int T  = N + nB;

    __nv_bfloat16 *valh, *vall, *qbh, *qbl, *kbh, *kbl, *vbh, *vbl, *ctxh, *ctxl, *wbhi, *wblo;
    int *off, *dest;
    cudaGetSymbolAddress((void**)&valh,  g_valh);
    cudaGetSymbolAddress((void**)&vall,  g_vall);
    cudaGetSymbolAddress((void**)&qbh,   g_qbh);
    cudaGetSymbolAddress((void**)&qbl,   g_qbl);
    cudaGetSymbolAddress((void**)&kbh,   g_kbh);
    cudaGetSymbolAddress((void**)&kbl,   g_kbl);
    cudaGetSymbolAddress((void**)&vbh,   g_vbh);
    cudaGetSymbolAddress((void**)&vbl,   g_vbl);
    cudaGetSymbolAddress((void**)&ctxh,  g_ctxh);
    cudaGetSymbolAddress((void**)&ctxl,  g_ctxl);
    cudaGetSymbolAddress((void**)&wbhi,  g_wbhi);
    cudaGetSymbolAddress((void**)&wblo,  g_wblo);
    cudaGetSymbolAddress((void**)&off,   g_off);
    cudaGetSymbolAddress((void**)&dest,  g_dest);

    cudaFuncSetAttribute(gemm_fused5,    cudaFuncAttributeMaxDynamicSharedMemorySize, FUSED_SMEM);
    cudaFuncSetAttribute(gemm_singleOut, cudaFuncAttributeMaxDynamicSharedMemorySize, GEMM_SMEM);
    cudaFuncSetAttribute(attn_tc_kernel, cudaFuncAttributeMaxDynamicSharedMemorySize, ATTN_TC_SMEM);
    cudaFuncSetAttribute(attn_kernel,    cudaFuncAttributeMaxDynamicSharedMemorySize, ATTN_SMEM);

    const int W = EDIM * EDIM;
    const float SCALE = 0.17677669529663688f;   // 1/sqrt(32)

    offsets_kernel<<<(nB + 256) / 256, 256>>>(batch, N, nB, off);
    wdecomp_kernel<<<(6 * W + 255) / 256, 256>>>(Wk, Wq, in_w, out_w, wbhi, wblo);
    gather_kernel<<<(T + 7) / 8, 256>>>(x, metal_x, batch, off, N, nB, valh, vall, dest);

    int tiles = (T + 63) / 64;

    // full projection chain: value -> q(scaled), k, v (head-major decomposed), one kernel
    gemm_fused5<<<tiles, 256, FUSED_SMEM>>>(valh, vall, wbhi, wblo, bk, bq, in_b,
                                            qbh, qbl, kbh, kbl, vbh, vbl, T, SCALE);

    dim3 agrid(nB, NHEAD);
    attn_tc_kernel<<<agrid, 320, ATTN_TC_SMEM>>>(qbh, qbl, kbh, kbl, vbh, vbl, ctxh, ctxl, off, T);
    attn_kernel<<<agrid, 192, ATTN_SMEM>>>(qbh, qbl, kbh, kbl, vbh, vbl, ctxh, ctxl, off, T);

    // ctx -> out (dest scatter)
    gemm_singleOut<<<tiles, 256, GEMM_SMEM>>>(ctxh, ctxl, wbhi + 5*W, wblo + 5*W, out_b, out, dest, T);
}

// round 16
// speedup vs baseline: 1.0455x; 1.0455x over previous
#include <cuda_runtime.h>
#include <cuda_bf16.h>
#include <cstdint>

#define EDIM   128
#define NHEAD  4
#define HD     32
#define MAXN   65536
#define MAXB   512
#define MAXT   (MAXN + MAXB)
#define LCAP   256      // scalar-fallback smem staging cap
#define LP     176      // tensor attention max L (fallback beyond)

// ---------------- scratch (decomposed bf16 hi/lo everywhere) ----------------
__device__ __nv_bfloat16 g_valh[(size_t)MAXT * EDIM];
__device__ __nv_bfloat16 g_vall[(size_t)MAXT * EDIM];
__device__ __nv_bfloat16 g_qbh [(size_t)MAXT * EDIM];   // head-major [H][T][32], scaled
__device__ __nv_bfloat16 g_qbl [(size_t)MAXT * EDIM];
__device__ __nv_bfloat16 g_kbh [(size_t)MAXT * EDIM];
__device__ __nv_bfloat16 g_kbl [(size_t)MAXT * EDIM];
__device__ __nv_bfloat16 g_vbh [(size_t)MAXT * EDIM];
__device__ __nv_bfloat16 g_vbl [(size_t)MAXT * EDIM];
__device__ __nv_bfloat16 g_ctxh[(size_t)MAXT * EDIM];   // token-major [T][128]
__device__ __nv_bfloat16 g_ctxl[(size_t)MAXT * EDIM];
__device__ __nv_bfloat16 g_wbhi[6 * EDIM * EDIM];       // Wk,Wq,in_q,in_k,in_v,out
__device__ __nv_bfloat16 g_wblo[6 * EDIM * EDIM];
__device__ int   g_off  [MAXB + 1];
__device__ int   g_dest [MAXT];

// ---------------- helpers ----------------
__device__ __forceinline__ uint32_t smem_u32(const void* p) {
    uint32_t a;
    asm("{ .reg .u64 t; cvta.to.shared.u64 t, %1; cvt.u32.u64 %0, t; }" : "=r"(a) : "l"(p));
    return a;
}
__device__ __forceinline__ void ldsm4(uint32_t* r, uint32_t addr) {
    asm volatile("ldmatrix.sync.aligned.m8n8.x4.shared.b16 {%0,%1,%2,%3}, [%4];"
                 : "=r"(r[0]), "=r"(r[1]), "=r"(r[2]), "=r"(r[3]) : "r"(addr));
}
__device__ __forceinline__ void ldsm4t(uint32_t* r, uint32_t addr) {
    asm volatile("ldmatrix.sync.aligned.m8n8.x4.trans.shared.b16 {%0,%1,%2,%3}, [%4];"
                 : "=r"(r[0]), "=r"(r[1]), "=r"(r[2]), "=r"(r[3]) : "r"(addr));
}
__device__ __forceinline__ void mma_bf16(float* d, const uint32_t* a, const uint32_t* b) {
    asm volatile("mma.sync.aligned.m16n8k16.row.col.f32.bf16.bf16.f32 "
                 "{%0,%1,%2,%3}, {%4,%5,%6,%7}, {%8,%9}, {%0,%1,%2,%3};"
                 : "+f"(d[0]), "+f"(d[1]), "+f"(d[2]), "+f"(d[3])
                 : "r"(a[0]), "r"(a[1]), "r"(a[2]), "r"(a[3]), "r"(b[0]), "r"(b[1]));
}
__device__ __forceinline__ uint32_t pack_bf2(float a, float b) {
    __nv_bfloat162 t = __floats2bfloat162_rn(a, b);
    return *(uint32_t*)&t;
}
__device__ __forceinline__ float bf16_rt(float x) {
    return __bfloat162float(__float2bfloat16(x));
}
__device__ __forceinline__ void cp16(uint32_t dst, const void* src, bool valid) {
    int sz = valid ? 16 : 0;
    asm volatile("cp.async.cg.shared.global [%0], [%1], 16, %2;"
                 :: "r"(dst), "l"(src), "r"(sz) : "memory");
}
#define CP_COMMIT() asm volatile("cp.async.commit_group;" ::: "memory")
#define CP_WAIT0()  asm volatile("cp.async.wait_group 0;" ::: "memory")

// ---------------- small setup kernels ----------------
__global__ void offsets_kernel(const int* __restrict__ batch, int N, int nB, int* __restrict__ off)
{
    int g = blockIdx.x * blockDim.x + threadIdx.x;
    if (g > nB) return;
    if (g == nB) { off[nB] = N; return; }
    int lo = 0, hi = N;
    while (lo < hi) { int m = (lo + hi) >> 1; if (batch[m] < g) lo = m + 1; else hi = m; }
    off[g] = lo;
}

__global__ void gather_kernel(const float* __restrict__ x, const float* __restrict__ mx,
                              const int* __restrict__ batch, const int* __restrict__ off,
                              int N, int nB,
                              __nv_bfloat16* __restrict__ valh, __nv_bfloat16* __restrict__ vall,
                              int* __restrict__ dest)
{
    int row  = blockIdx.x * 8 + (threadIdx.x >> 5);
    int lane = threadIdx.x & 31;
    const float* src = nullptr;
    int tok = -1, drow = 0;
    if (row < N) {
        int g = batch[row]; tok = row + g + 1; drow = row;
        src = x + (size_t)row * EDIM;
    } else if (row < N + nB) {
        int g = row - N; tok = off[g] + g; drow = N + g;
        src = mx + (size_t)g * EDIM;
    } else return;
    float4 v4 = *(const float4*)(src + lane * 4);
    float h0 = bf16_rt(v4.x), h1 = bf16_rt(v4.y), h2 = bf16_rt(v4.z), h3 = bf16_rt(v4.w);
    size_t o = (size_t)tok * EDIM + lane * 4;
    *(uint2*)(valh + o) = make_uint2(pack_bf2(h0, h1), pack_bf2(h2, h3));
    *(uint2*)(vall + o) = make_uint2(pack_bf2(v4.x - h0, v4.y - h1), pack_bf2(v4.z - h2, v4.w - h3));
    if (lane == 0) dest[tok] = drow;
}

__global__ void wdecomp_kernel(const float* __restrict__ Wk, const float* __restrict__ Wq,
                               const float* __restrict__ in_w, const float* __restrict__ out_w,
                               __nv_bfloat16* __restrict__ bhi, __nv_bfloat16* __restrict__ blo)
{
    int idx = blockIdx.x * 256 + threadIdx.x;
    if (idx >= 6 * EDIM * EDIM) return;
    int slab = idx >> 14, r = idx & 16383;
    float v = (slab == 0) ? Wk[r] : (slab == 1) ? Wq[r]
            : (slab < 5)  ? in_w[(size_t)(slab - 2) * EDIM * EDIM + r] : out_w[r];
    __nv_bfloat16 h = __float2bfloat16(v);
    bhi[idx] = h;
    blo[idx] = __float2bfloat16(v - __bfloat162float(h));
}

// ================= fused5: cp.async double-buffered weights, A resident (R12 config) =================
// 192KB smem, 1 CTA/SM. A: hi@0 lo@16K. X: hi@32K lo@48K. B0: hi@64K lo@96K. B1: hi@128K lo@160K.
#define FA_HI  0
#define FA_LO  16384
#define FX_HI  32768
#define FX_LO  49152
#define B0_HI  65536
#define B0_LO  98304
#define B1_HI  131072
#define B1_LO  163840
#define FUSED_SMEM 196608

__device__ __forceinline__ void ca_stage_A(const __nv_bfloat16* __restrict__ Ah,
                                           const __nv_bfloat16* __restrict__ Al,
                                           int tile0, int T, uint32_t sb, int tid)
{
    #pragma unroll
    for (int i = 0; i < 4; i++) {
        int f   = tid + i * 256;
        int row = f >> 4;
        int grp = f & 15;
        bool v  = (tile0 + row) < T;
        int srow = v ? (tile0 + row) : 0;
        uint32_t off = row * 256 + ((grp ^ (row & 7)) << 4);
        cp16(sb + FA_HI + off, Ah + (size_t)srow * EDIM + grp * 8, v);
        cp16(sb + FA_LO + off, Al + (size_t)srow * EDIM + grp * 8, v);
    }
}

__device__ __forceinline__ void ca_stage_B(const __nv_bfloat16* __restrict__ Bhi,
                                           const __nv_bfloat16* __restrict__ Blo,
                                           uint32_t sb, int tid, uint32_t rbHi, uint32_t rbLo)
{
    #pragma unroll
    for (int i = 0; i < 8; i++) {
        int f   = tid + i * 256;
        int row = f >> 4;
        int grp = f & 15;
        uint32_t off = row * 256 + ((grp ^ (row & 7)) << 4);
        cp16(sb + rbHi + off, Bhi + (size_t)row * EDIM + grp * 8, true);
        cp16(sb + rbLo + off, Blo + (size_t)row * EDIM + grp * 8, true);
    }
}

// 3xBF16 compute: acc[2][4][4] per warp (tile 32x32 at (wm*32, wn*32)), full K=128 (R12 version)
__device__ __forceinline__ void compute_full(uint32_t sb, float acc[2][4][4],
                                             uint32_t aHi, uint32_t aLo,
                                             uint32_t bHi, uint32_t bLo,
                                             int wid, int lane)
{
    const int wm = wid & 1, wn = wid >> 1;
    const int m0 = wm * 32, n0 = wn * 32;
    const int lr = lane & 15, lc = lane >> 4;

    #pragma unroll
    for (int im = 0; im < 2; im++)
        #pragma unroll
        for (int in = 0; in < 4; in++)
            #pragma unroll
            for (int c = 0; c < 4; c++) acc[im][in][c] = 0.f;

    #pragma unroll 1
    for (int k16 = 0; k16 < 8; k16++) {
        const int kb = k16 * 2 + lc;
        uint32_t ah[2][4], al[2][4], bh[4][2], bl[4][2];
        #pragma unroll
        for (int im = 0; im < 2; im++) {
            int row = m0 + im * 16 + lr;
            uint32_t off = row * 256 + ((kb ^ (row & 7)) << 4);
            ldsm4(ah[im], sb + aHi + off);
            ldsm4(al[im], sb + aLo + off);
        }
        #pragma unroll
        for (int p = 0; p < 2; p++) {
            int row = n0 + p * 16 + lr;
            uint32_t off = row * 256 + ((kb ^ (row & 7)) << 4);
            uint32_t rh[4], rl[4];
            ldsm4(rh, sb + bHi + off);
            ldsm4(rl, sb + bLo + off);
            bh[2*p+0][0] = rh[0]; bh[2*p+0][1] = rh[2];
            bh[2*p+1][0] = rh[1]; bh[2*p+1][1] = rh[3];
            bl[2*p+0][0] = rl[0]; bl[2*p+0][1] = rl[2];
            bl[2*p+1][0] = rl[1]; bl[2*p+1][1] = rl[3];
        }
        #pragma unroll
        for (int im = 0; im < 2; im++)
            #pragma unroll
            for (int in = 0; in < 4; in++) {
                mma_bf16(acc[im][in], ah[im], bh[in]);
                mma_bf16(acc[im][in], ah[im], bl[in]);
                mma_bf16(acc[im][in], al[im], bh[in]);
            }
    }
}

// epilogue: bias+relu, decompose, write to smem X region in A-stage format
__device__ __forceinline__ void epi_to_X(const float acc[2][4][4], const float* __restrict__ bias,
                                         char* smem, int wid, int lane)
{
    const int wm = wid & 1, wn = wid >> 1;
    const int m0 = wm * 32, n0 = wn * 32;
    const int gid = lane >> 2, tig = lane & 3;
    #pragma unroll
    for (int in = 0; in < 4; in++) {
        int col = n0 + in * 8 + tig * 2;
        float2 b2 = *(const float2*)(bias + col);
        int grp = col >> 3, within = (col & 7) * 2;
        #pragma unroll
        for (int im = 0; im < 2; im++)
            #pragma unroll
            for (int rh = 0; rh < 2; rh++) {
                int row = m0 + im * 16 + gid + rh * 8;
                float v0 = fmaxf(acc[im][in][rh*2+0] + b2.x, 0.f);
                float v1 = fmaxf(acc[im][in][rh*2+1] + b2.y, 0.f);
                float h0 = bf16_rt(v0), h1 = bf16_rt(v1);
                uint32_t off = row * 256 + ((grp ^ (row & 7)) << 4) + within;
                *(uint32_t*)(smem + FX_HI + off) = pack_bf2(h0, h1);
                *(uint32_t*)(smem + FX_LO + off) = pack_bf2(v0 - h0, v1 - h1);
            }
    }
}

// epilogue: decomposed head-major [H][T][32] with scale
__device__ __forceinline__ void epi_head_decomp(const float acc[2][4][4], const float* __restrict__ bias,
                                                __nv_bfloat16* __restrict__ Ch, __nv_bfloat16* __restrict__ Cl,
                                                int tile0, int T, float scale, int wid, int lane)
{
    const int wm = wid & 1, wn = wid >> 1;
    const int m0 = wm * 32, n0 = wn * 32;
    const int gid = lane >> 2, tig = lane & 3;
    #pragma unroll
    for (int in = 0; in < 4; in++) {
        int col = n0 + in * 8 + tig * 2;
        float2 b2 = *(const float2*)(bias + col);
        int hh = col >> 5, ci = col & 31;
        #pragma unroll
        for (int im = 0; im < 2; im++)
            #pragma unroll
            for (int rh = 0; rh < 2; rh++) {
                int row = m0 + im * 16 + gid + rh * 8;
                if (tile0 + row >= T) continue;
                float v0 = (acc[im][in][rh*2+0] + b2.x) * scale;
                float v1 = (acc[im][in][rh*2+1] + b2.y) * scale;
                float h0 = bf16_rt(v0), h1 = bf16_rt(v1);
                size_t o = ((size_t)hh * T + tile0 + row) * HD + ci;
                *(uint32_t*)(Ch + o) = pack_bf2(h0, h1);
                *(uint32_t*)(Cl + o) = pack_bf2(v0 - h0, v1 - h1);
            }
    }
}

__global__ __launch_bounds__(256, 1)
void gemm_fused5(const __nv_bfloat16* __restrict__ Avh, const __nv_bfloat16* __restrict__ Avl,
                 const __nv_bfloat16* __restrict__ wbhi, const __nv_bfloat16* __restrict__ wblo,
                 const float* __restrict__ bk, const float* __restrict__ bq,
                 const float* __restrict__ in_b,
                 __nv_bfloat16* __restrict__ qbh, __nv_bfloat16* __restrict__ qbl,
                 __nv_bfloat16* __restrict__ kbh, __nv_bfloat16* __restrict__ kbl,
                 __nv_bfloat16* __restrict__ vbh, __nv_bfloat16* __restrict__ vbl,
                 int T, float scaleQ)
{
    extern __shared__ char smem[];
    const uint32_t sb = smem_u32(smem);
    const int tid = threadIdx.x, wid = tid >> 5, lane = tid & 31;
    const int tile0 = blockIdx.x * 64;
    const int W = EDIM * EDIM;
    float acc[2][4][4];

    // initial: A(value) + Wk
    ca_stage_A(Avh, Avl, tile0, T, sb, tid);
    ca_stage_B(wbhi + 0*W, wblo + 0*W, sb, tid, B0_HI, B0_LO);
    CP_COMMIT(); CP_WAIT0();
    __syncthreads();

    // G1: kin = relu(value@Wk^T)   [A,B0]; prefetch in_k -> B1
    ca_stage_B(wbhi + 3*W, wblo + 3*W, sb, tid, B1_HI, B1_LO); CP_COMMIT();
    compute_full(sb, acc, FA_HI, FA_LO, B0_HI, B0_LO, wid, lane);
    epi_to_X(acc, bk, smem, wid, lane);
    CP_WAIT0(); __syncthreads();

    // G2: k = kin@in_k^T           [X,B1]; prefetch Wq -> B0
    ca_stage_B(wbhi + 1*W, wblo + 1*W, sb, tid, B0_HI, B0_LO); CP_COMMIT();
    compute_full(sb, acc, FX_HI, FX_LO, B1_HI, B1_LO, wid, lane);
    epi_head_decomp(acc, in_b + 128, kbh, kbl, tile0, T, 1.0f, wid, lane);
    CP_WAIT0(); __syncthreads();

    // G3: qin = relu(value@Wq^T)   [A,B0]; prefetch in_q -> B1
    ca_stage_B(wbhi + 2*W, wblo + 2*W, sb, tid, B1_HI, B1_LO); CP_COMMIT();
    compute_full(sb, acc, FA_HI, FA_LO, B0_HI, B0_LO, wid, lane);
    epi_to_X(acc, bq, smem, wid, lane);
    CP_WAIT0(); __syncthreads();

    // G4: q = (qin@in_q^T)*scale   [X,B1]; prefetch in_v -> B0
    ca_stage_B(wbhi + 4*W, wblo + 4*W, sb, tid, B0_HI, B0_LO); CP_COMMIT();
    compute_full(sb, acc, FX_HI, FX_LO, B1_HI, B1_LO, wid, lane);
    epi_head_decomp(acc, in_b, qbh, qbl, tile0, T, scaleQ, wid, lane);
    CP_WAIT0(); __syncthreads();

    // G5: v = value@in_v^T         [A,B0]
    compute_full(sb, acc, FA_HI, FA_LO, B0_HI, B0_LO, wid, lane);
    epi_head_decomp(acc, in_b + 256, vbh, vbl, tile0, T, 1.0f, wid, lane);
}

// ================= out projection: ctx(decomposed) -> fp32 out with dest scatter =================
#define GA_HI 0
#define GA_LO 16384
#define GB_HI 32768
#define GB_LO 65536
#define GEMM_SMEM 98304

__global__ __launch_bounds__(256, 2)
void gemm_singleOut(const __nv_bfloat16* __restrict__ Ah, const __nv_bfloat16* __restrict__ Al,
                    const __nv_bfloat16* __restrict__ Bhi, const __nv_bfloat16* __restrict__ Blo,
                    const float* __restrict__ bias, float* __restrict__ C,
                    const int* __restrict__ dest, int T)
{
    extern __shared__ char smem[];
    const uint32_t sb = smem_u32(smem);
    const int tid = threadIdx.x, wid = tid >> 5, lane = tid & 31;
    const int tile0 = blockIdx.x * 64;

    #pragma unroll
    for (int i = 0; i < 4; i++) {
        int f   = tid + i * 256;
        int row = f >> 4;
        int grp = f & 15;
        bool v  = (tile0 + row) < T;
        int srow = v ? (tile0 + row) : 0;
        uint32_t off = row * 256 + ((grp ^ (row & 7)) << 4);
        cp16(sb + GA_HI + off, Ah + (size_t)srow * EDIM + grp * 8, v);
        cp16(sb + GA_LO + off, Al + (size_t)srow * EDIM + grp * 8, v);
    }
    #pragma unroll
    for (int i = 0; i < 8; i++) {
        int f   = tid + i * 256;
        int row = f >> 4;
        int grp = f & 15;
        uint32_t off = row * 256 + ((grp ^ (row & 7)) << 4);
        cp16(sb + GB_HI + off, Bhi + (size_t)row * EDIM + grp * 8, true);
        cp16(sb + GB_LO + off, Blo + (size_t)row * EDIM + grp * 8, true);
    }
    CP_COMMIT(); CP_WAIT0();
    __syncthreads();

    float acc[2][4][4];
    compute_full(sb, acc, GA_HI, GA_LO, GB_HI, GB_LO, wid, lane);

    const int wm = wid & 1, wn = wid >> 1;
    const int m0 = wm * 32, n0 = wn * 32;
    const int gid = lane >> 2, tig = lane & 3;
    #pragma unroll
    for (int in = 0; in < 4; in++) {
        int col = n0 + in * 8 + tig * 2;
        float2 b2 = *(const float2*)(bias + col);
        #pragma unroll
        for (int im = 0; im < 2; im++)
            #pragma unroll
            for (int rh = 0; rh < 2; rh++) {
                int row = m0 + im * 16 + gid + rh * 8;
                if (tile0 + row >= T) continue;
                int orow = dest[tile0 + row];
                *(float2*)(C + (size_t)orow * EDIM + col) =
                    make_float2(acc[im][in][rh*2+0] + b2.x, acc[im][in][rh*2+1] + b2.y);
            }
    }
}

// ================= flash attention: 320 threads, 2-k-tile batched softmax =================
// smem: Q,K,V hi/lo, each [192][32] bf16 pitch 40 elems (80B) = 15360B; total 92160B -> 2 CTAs/SM.
#define SQ_HI 0
#define SQ_LO 15360
#define SK_HI 30720
#define SK_LO 46080
#define SV_HI 61440
#define SV_LO 76800
#define ATTN_TC_SMEM 92160

__global__ __launch_bounds__(320, 2)
void attn_tc_kernel(const __nv_bfloat16* __restrict__ qbh, const __nv_bfloat16* __restrict__ qbl,
                    const __nv_bfloat16* __restrict__ kbh, const __nv_bfloat16* __restrict__ kbl,
                    const __nv_bfloat16* __restrict__ vbh, const __nv_bfloat16* __restrict__ vbl,
                    __nv_bfloat16* __restrict__ ctxh, __nv_bfloat16* __restrict__ ctxl,
                    const int* __restrict__ off, int T)
{
    extern __shared__ char smem[];
    const uint32_t sb = smem_u32(smem);
    int g = blockIdx.x, h = blockIdx.y;
    int t0 = off[g] + g;
    int L  = off[g + 1] - off[g] + 1;
    if (L > LP) return;                      // scalar fallback handles
    int Lpad = (L + 31) & ~31;               // pad to 2-tile (32-key) granularity, <=192

    const int tid = threadIdx.x;
    const char* qh_b = (const char*)(qbh + (size_t)h * T * HD);
    const char* ql_b = (const char*)(qbl + (size_t)h * T * HD);
    const char* kh_b = (const char*)(kbh + (size_t)h * T * HD);
    const char* kl_b = (const char*)(kbl + (size_t)h * T * HD);
    const char* vh_b = (const char*)(vbh + (size_t)h * T * HD);
    const char* vl_b = (const char*)(vbl + (size_t)h * T * HD);

    for (int m = tid; m < Lpad; m += 320) {
        if (m < L) {
            size_t go = (size_t)(t0 + m) * 64;
            #pragma unroll
            for (int g4 = 0; g4 < 4; g4++) {
                uint32_t so = (uint32_t)m * 80 + g4 * 16;
                *(uint4*)(smem + SQ_HI + so) = *(const uint4*)(qh_b + go + g4 * 16);
                *(uint4*)(smem + SQ_LO + so) = *(const uint4*)(ql_b + go + g4 * 16);
                *(uint4*)(smem + SK_HI + so) = *(const uint4*)(kh_b + go + g4 * 16);
                *(uint4*)(smem + SK_LO + so) = *(const uint4*)(kl_b + go + g4 * 16);
                *(uint4*)(smem + SV_HI + so) = *(const uint4*)(vh_b + go + g4 * 16);
                *(uint4*)(smem + SV_LO + so) = *(const uint4*)(vl_b + go + g4 * 16);
            }
        } else {
            uint4 z = make_uint4(0,0,0,0);
            #pragma unroll
            for (int g4 = 0; g4 < 4; g4++) {
                uint32_t so = (uint32_t)m * 80 + g4 * 16;
                *(uint4*)(smem + SQ_HI + so) = z; *(uint4*)(smem + SQ_LO + so) = z;
                *(uint4*)(smem + SK_HI + so) = z; *(uint4*)(smem + SK_LO + so) = z;
                *(uint4*)(smem + SV_HI + so) = z; *(uint4*)(smem + SV_LO + so) = z;
            }
        }
    }
    __syncthreads();

    const int w = tid >> 5, lane = tid & 31;
    const int lr = lane & 15, lc = lane >> 4;
    const int npair = (L + 31) >> 5;         // 32-key pairs
    const uint32_t vrow = ((lane >> 3) & 1) * 8 + (lane & 7);
    const uint32_t vcol = (lane >> 4) * 8;
    const int tig2 = (lane & 3) << 1;

    for (int m0 = w * 16; m0 < L; m0 += 160) {
        uint32_t qfh[2][4], qfl[2][4];
        #pragma unroll
        for (int s = 0; s < 2; s++) {
            uint32_t a = sb + SQ_HI + (uint32_t)(m0 + lr) * 80 + s * 32 + lc * 16;
            ldsm4(qfh[s], a);
            ldsm4(qfl[s], a + (SQ_LO - SQ_HI));
        }
        float mr0 = -1e30f, mr1 = -1e30f, l0 = 0.f, l1 = 0.f;
        float cacc[4][4];
        #pragma unroll
        for (int n = 0; n < 4; n++) { cacc[n][0]=0.f; cacc[n][1]=0.f; cacc[n][2]=0.f; cacc[n][3]=0.f; }

        #pragma unroll 1
        for (int kp = 0; kp < npair; kp++) {
            // ---- S for 2 k-tiles (32 keys) ----
            float s[2][2][4];
            #pragma unroll
            for (int t = 0; t < 2; t++) {
                s[t][0][0]=0.f; s[t][0][1]=0.f; s[t][0][2]=0.f; s[t][0][3]=0.f;
                s[t][1][0]=0.f; s[t][1][1]=0.f; s[t][1][2]=0.f; s[t][1][3]=0.f;
                int kt = 2*kp + t;
                #pragma unroll
                for (int st = 0; st < 2; st++) {
                    uint32_t a = sb + SK_HI + (uint32_t)(kt * 16 + lr) * 80 + st * 32 + lc * 16;
                    uint32_t kh[4], kl[4];
                    ldsm4(kh, a);
                    ldsm4(kl, a + (SK_LO - SK_HI));
                    uint32_t bh0[2] = {kh[0], kh[2]}, bh1[2] = {kh[1], kh[3]};
                    uint32_t bl0[2] = {kl[0], kl[2]}, bl1[2] = {kl[1], kl[3]};
                    mma_bf16(s[t][0], qfh[st], bh0); mma_bf16(s[t][0], qfh[st], bl0); mma_bf16(s[t][0], qfl[st], bh0);
                    mma_bf16(s[t][1], qfh[st], bh1); mma_bf16(s[t][1], qfh[st], bl1); mma_bf16(s[t][1], qfl[st], bh1);
                }
            }
            // ---- mask padded keys (only last pair) ----
            if (kp == npair - 1) {
                #pragma unroll
                for (int t = 0; t < 2; t++)
                    #pragma unroll
                    for (int half = 0; half < 2; half++) {
                        int ck = (2*kp + t) * 16 + half * 8 + tig2;
                        if (ck >= L)     { s[t][half][0] = -1e30f; s[t][half][2] = -1e30f; }
                        if (ck + 1 >= L) { s[t][half][1] = -1e30f; s[t][half][3] = -1e30f; }
                    }
            }
            // ---- ONE online softmax update for 32 keys ----
            float tm0 = fmaxf(fmaxf(fmaxf(s[0][0][0], s[0][0][1]), fmaxf(s[0][1][0], s[0][1][1])),
                              fmaxf(fmaxf(s[1][0][0], s[1][0][1]), fmaxf(s[1][1][0], s[1][1][1])));
            float tm1 = fmaxf(fmaxf(fmaxf(s[0][0][2], s[0][0][3]), fmaxf(s[0][1][2], s[0][1][3])),
                              fmaxf(fmaxf(s[1][0][2], s[1][0][3]), fmaxf(s[1][1][2], s[1][1][3])));
            tm0 = fmaxf(tm0, __shfl_xor_sync(0xffffffffu, tm0, 1));
            tm0 = fmaxf(tm0, __shfl_xor_sync(0xffffffffu, tm0, 2));
            tm1 = fmaxf(tm1, __shfl_xor_sync(0xffffffffu, tm1, 1));
            tm1 = fmaxf(tm1, __shfl_xor_sync(0xffffffffu, tm1, 2));
            float nm0 = fmaxf(mr0, tm0), nm1 = fmaxf(mr1, tm1);
            float c0 = __expf(mr0 - nm0), c1 = __expf(mr1 - nm1);
            mr0 = nm0; mr1 = nm1;
            float rs0 = 0.f, rs1 = 0.f;
            #pragma unroll
            for (int t = 0; t < 2; t++)
                #pragma unroll
                for (int half = 0; half < 2; half++) {
                    s[t][half][0] = __expf(s[t][half][0] - nm0);
                    s[t][half][1] = __expf(s[t][half][1] - nm0);
                    s[t][half][2] = __expf(s[t][half][2] - nm1);
                    s[t][half][3] = __expf(s[t][half][3] - nm1);
                    rs0 += s[t][half][0] + s[t][half][1];
                    rs1 += s[t][half][2] + s[t][half][3];
                }
            rs0 += __shfl_xor_sync(0xffffffffu, rs0, 1);
            rs0 += __shfl_xor_sync(0xffffffffu, rs0, 2);
            rs1 += __shfl_xor_sync(0xffffffffu, rs1, 1);
            rs1 += __shfl_xor_sync(0xffffffffu, rs1, 2);
            l0 = l0 * c0 + rs0;
            l1 = l1 * c1 + rs1;
            #pragma unroll
            for (int n = 0; n < 4; n++) {
                cacc[n][0] *= c0; cacc[n][1] *= c0;
                cacc[n][2] *= c1; cacc[n][3] *= c1;
            }
            // ---- PV for both tiles ----
            #pragma unroll
            for (int t = 0; t < 2; t++) {
                int kt = 2*kp + t;
                uint32_t pfh[4], pfl[4];
                #pragma unroll
                for (int half = 0; half < 2; half++) {
                    float h0 = bf16_rt(s[t][half][0]), h1 = bf16_rt(s[t][half][1]);
                    float h2 = bf16_rt(s[t][half][2]), h3 = bf16_rt(s[t][half][3]);
                    pfh[2*half + 0] = pack_bf2(h0, h1);
                    pfh[2*half + 1] = pack_bf2(h2, h3);
                    pfl[2*half + 0] = pack_bf2(s[t][half][0] - h0, s[t][half][1] - h1);
                    pfl[2*half + 1] = pack_bf2(s[t][half][2] - h2, s[t][half][3] - h3);
                }
                #pragma unroll
                for (int ng = 0; ng < 2; ng++) {
                    uint32_t a = sb + SV_HI + (uint32_t)(kt * 16 + vrow) * 80 + (ng * 16 + vcol) * 2;
                    uint32_t vh[4], vl[4];
                    ldsm4t(vh, a);
                    ldsm4t(vl, a + (SV_LO - SV_HI));
                    uint32_t bh0[2] = {vh[0], vh[1]}, bh1[2] = {vh[2], vh[3]};
                    uint32_t bl0[2] = {vl[0], vl[1]}, bl1[2] = {vl[2], vl[3]};
                    mma_bf16(cacc[2*ng],   pfh, bh0);
                    mma_bf16(cacc[2*ng],   pfh, bl0);
                    mma_bf16(cacc[2*ng],   pfl, bh0);
                    mma_bf16(cacc[2*ng+1], pfh, bh1);
                    mma_bf16(cacc[2*ng+1], pfh, bl1);
                    mma_bf16(cacc[2*ng+1], pfl, bh1);
                }
            }
        }
        // ---- normalize + store ctx decomposed ----
        float i0 = 1.f / l0, i1 = 1.f / l1;
        int r0 = m0 + (lane >> 2), r1 = r0 + 8;
        #pragma unroll
        for (int nt = 0; nt < 4; nt++) {
            int col = nt * 8 + tig2;
            if (r0 < L) {
                float c0v = cacc[nt][0] * i0, c1v = cacc[nt][1] * i0;
                float h0 = bf16_rt(c0v), h1 = bf16_rt(c1v);
                size_t o = (size_t)(t0 + r0) * EDIM + h * HD + col;
                *(uint32_t*)(ctxh + o) = pack_bf2(h0, h1);
                *(uint32_t*)(ctxl + o) = pack_bf2(c0v - h0, c1v - h1);
            }
            if (r1 < L) {
                float c0v = cacc[nt][2] * i1, c1v = cacc[nt][3] * i1;
                float h0 = bf16_rt(c0v), h1 = bf16_rt(c1v);
                size_t o = (size_t)(t0 + r1) * EDIM + h * HD + col;
                *(uint32_t*)(ctxh + o) = pack_bf2(h0, h1);
                *(uint32_t*)(ctxl + o) = pack_bf2(c0v - h0, c1v - h1);
            }
        }
    }
}

// ---------------- scalar fallback attention (only L > LP) ----------------
#define ATTN_SMEM (2 * LCAP * HD * 4)

__global__ __launch_bounds__(192)
void attn_kernel(const __nv_bfloat16* __restrict__ qbh, const __nv_bfloat16* __restrict__ qbl,
                 const __nv_bfloat16* __restrict__ kbh, const __nv_bfloat16* __restrict__ kbl,
                 const __nv_bfloat16* __restrict__ vbh, const __nv_bfloat16* __restrict__ vbl,
                 __nv_bfloat16* __restrict__ ctxh, __nv_bfloat16* __restrict__ ctxl,
                 const int* __restrict__ off, int T)
{
    extern __shared__ float sm[];
    float* Ks = sm;
    float* Vs = sm + LCAP * HD;

    int g = blockIdx.x, h = blockIdx.y;
    int t0 = off[g] + g;
    int L  = off[g + 1] - off[g] + 1;
    if (L <= LP) return;
    int Ls = L < LCAP ? L : LCAP;
    int tid = threadIdx.x;

    const __nv_bfloat16* kh = kbh + (size_t)h * T * HD;
    const __nv_bfloat16* kl = kbl + (size_t)h * T * HD;
    const __nv_bfloat16* vh = vbh + (size_t)h * T * HD;
    const __nv_bfloat16* vl = vbl + (size_t)h * T * HD;
    const __nv_bfloat16* qh = qbh + (size_t)h * T * HD;
    const __nv_bfloat16* ql = qbl + (size_t)h * T * HD;

    for (int idx = tid; idx < Ls * HD; idx += blockDim.x) {
        size_t o = (size_t)t0 * HD + idx;
        Ks[idx] = __bfloat162float(kh[o]) + __bfloat162float(kl[o]);
        Vs[idx] = __bfloat162float(vh[o]) + __bfloat162float(vl[o]);
    }
    __syncthreads();

    for (int qi = tid; qi < L; qi += blockDim.x) {
        float qr[32];
        size_t qo = (size_t)(t0 + qi) * HD;
        #pragma unroll
        for (int j = 0; j < 32; j++)
            qr[j] = __bfloat162float(qh[qo + j]) + __bfloat162float(ql[qo + j]);
        float mx = -1e30f, s = 0.f;
        float acc[32];
        #pragma unroll
        for (int j = 0; j < 32; j++) acc[j] = 0.f;
        for (int mk = 0; mk < L; mk++) {
            float kr[32];
            if (mk < Ls) {
                #pragma unroll
                for (int j = 0; j < 32; j++) kr[j] = Ks[mk * HD + j];
            } else {
                size_t o = (size_t)(t0 + mk) * HD;
                #pragma unroll
                for (int j = 0; j < 32; j++)
                    kr[j] = __bfloat162float(kh[o + j]) + __bfloat162float(kl[o + j]);
            }
            float d0 = 0.f, d1 = 0.f, d2 = 0.f, d3 = 0.f;
            #pragma unroll
            for (int j4 = 0; j4 < 8; j4++) {
                d0 += qr[j4*4+0] * kr[j4*4+0]; d1 += qr[j4*4+1] * kr[j4*4+1];
                d2 += qr[j4*4+2] * kr[j4*4+2]; d3 += qr[j4*4+3] * kr[j4*4+3];
            }
            float xv = (d0 + d1) + (d2 + d3);
            float p;
            if (xv > mx) {
                float c = __expf(mx - xv);
                s *= c;
                #pragma unroll
                for (int j = 0; j < 32; j++) acc[j] *= c;
                mx = xv; p = 1.f;
            } else p = __expf(xv - mx);
            s += p;
            if (mk < Ls) {
                #pragma unroll
                for (int j = 0; j < 32; j++) acc[j] += p * Vs[mk * HD + j];
            } else {
                size_t o = (size_t)(t0 + mk) * HD;
                #pragma unroll
                for (int j = 0; j < 32; j++)
                    acc[j] += p * (__bfloat162float(vh[o + j]) + __bfloat162float(vl[o + j]));
            }
        }
        float inv = 1.f / s;
        size_t co = (size_t)(t0 + qi) * EDIM + h * HD;
        #pragma unroll
        for (int j2 = 0; j2 < 16; j2++) {
            float c0 = acc[j2*2+0] * inv, c1 = acc[j2*2+1] * inv;
            float h0 = bf16_rt(c0), h1 = bf16_rt(c1);
            *(uint32_t*)(ctxh + co + j2*2) = pack_bf2(h0, h1);
            *(uint32_t*)(ctxl + co + j2*2) = pack_bf2(c0 - h0, c1 - h1);
        }
    }
}

// ---------------- launch ----------------
extern "C" void kernel_launch(void* const* d_in, const int* in_sizes, int n_in,
                              void* d_out, int out_size)
{
    const float* x       = (const float*)d_in[0];
    const float* metal_x = (const float*)d_in[1];
    const int*   batch   = (const int*)  d_in[2];
    const float* Wk      = (const float*)d_in[3];
    const float* bk      = (const float*)d_in[4];
    const float* Wq      = (const float*)d_in[5];
    const float* bq      = (const float*)d_in[6];
    const float* in_w    = (const float*)d_in[7];
    const float* in_b    = (const float*)d_in[8];
    const float* out_w   = (const float*)d_in[9];
    const float* out_b   = (const float*)d_in[10];
    float* out = (float*)d_out;

    int N  = in_sizes[0] / EDIM;
    int nB = in_sizes[1] / EDIM;
    int T  = N + nB;

    __nv_bfloat16 *valh, *vall, *qbh, *qbl, *kbh, *kbl, *vbh, *vbl, *ctxh, *ctxl, *wbhi, *wblo;
    int *off, *dest;
    cudaGetSymbolAddress((void**)&valh,  g_valh);
    cudaGetSymbolAddress((void**)&vall,  g_vall);
    cudaGetSymbolAddress((void**)&qbh,   g_qbh);
    cudaGetSymbolAddress((void**)&qbl,   g_qbl);
    cudaGetSymbolAddress((void**)&kbh,   g_kbh);
    cudaGetSymbolAddress((void**)&kbl,   g_kbl);
    cudaGetSymbolAddress((void**)&vbh,   g_vbh);
    cudaGetSymbolAddress((void**)&vbl,   g_vbl);
    cudaGetSymbolAddress((void**)&ctxh,  g_ctxh);
    cudaGetSymbolAddress((void**)&ctxl,  g_ctxl);
    cudaGetSymbolAddress((void**)&wbhi,  g_wbhi);
    cudaGetSymbolAddress((void**)&wblo,  g_wblo);
    cudaGetSymbolAddress((void**)&off,   g_off);
    cudaGetSymbolAddress((void**)&dest,  g_dest);

    cudaFuncSetAttribute(gemm_fused5,    cudaFuncAttributeMaxDynamicSharedMemorySize, FUSED_SMEM);
    cudaFuncSetAttribute(gemm_singleOut, cudaFuncAttributeMaxDynamicSharedMemorySize, GEMM_SMEM);
    cudaFuncSetAttribute(attn_tc_kernel, cudaFuncAttributeMaxDynamicSharedMemorySize, ATTN_TC_SMEM);
    cudaFuncSetAttribute(attn_kernel,    cudaFuncAttributeMaxDynamicSharedMemorySize, ATTN_SMEM);

    const int W = EDIM * EDIM;
    const float SCALE = 0.17677669529663688f;   // 1/sqrt(32)

    offsets_kernel<<<(nB + 256) / 256, 256>>>(batch, N, nB, off);
    wdecomp_kernel<<<(6 * W + 255) / 256, 256>>>(Wk, Wq, in_w, out_w, wbhi, wblo);
    gather_kernel<<<(T + 7) / 8, 256>>>(x, metal_x, batch, off, N, nB, valh, vall, dest);

    int tiles = (T + 63) / 64;

    // full projection chain: value -> q(scaled), k, v (head-major decomposed), one kernel
    gemm_fused5<<<tiles, 256, FUSED_SMEM>>>(valh, vall, wbhi, wblo, bk, bq, in_b,
                                            qbh, qbl, kbh, kbl, vbh, vbl, T, SCALE);

    dim3 agrid(nB, NHEAD);
    attn_tc_kernel<<<agrid, 320, ATTN_TC_SMEM>>>(qbh, qbl, kbh, kbl, vbh, vbl, ctxh, ctxl, off, T);
    attn_kernel<<<agrid, 192, ATTN_SMEM>>>(qbh, qbl, kbh, kbl, vbh, vbl, ctxh, ctxl, off, T);

    // ctx -> out (dest scatter)
    gemm_singleOut<<<tiles, 256, GEMM_SMEM>>>(ctxh, ctxl, wbhi + 5*W, wblo + 5*W, out_b, out, dest, T);
}